// round 7
// baseline (speedup 1.0000x reference)
#include <cuda_runtime.h>
#include <cuda_bf16.h>
#include <cstdint>
#include <math.h>

#define F   128
#define R   32
#define TP  128      // pairs per tile (8 warps x 16 rows)
#define NT  256

// ---------------------------------------------------------------- scratch
__device__ float g_h  [100000 * 128];
__device__ float g_acc[100000 * 128];
__device__ unsigned char g_W1T[2][10240];   // Wf1^T [n=128][k=32] bf16 hi/lo, 80B rows (conflict-free)
__device__ unsigned char g_W2T[2][32768];   // Wf2^T [n=128][k=128] bf16 hi/lo, 256B rows, XOR-swizzled

// ---------------------------------------------------------------- helpers
__device__ __forceinline__ uint32_t smem_u32(const void* p) {
    uint32_t a;
    asm("{ .reg .u64 t; cvta.to.shared.u64 t, %1; cvt.u32.u64 %0, t; }" : "=r"(a) : "l"(p));
    return a;
}
__device__ __forceinline__ float sspf(float x) {
    float e = __expf(-fabsf(x));
    return fmaxf(x, 0.0f) + __logf(1.0f + e) - 0.6931471805599453f;
}
__device__ __forceinline__ void red_add_v2(float* p, float a, float b) {
    asm volatile("red.global.add.v2.f32 [%0], {%1,%2};"
                 :: "l"(p), "f"(a), "f"(b) : "memory");
}
__device__ __forceinline__ void split_pack(float a, float b, uint32_t& hi, uint32_t& lo) {
    __nv_bfloat16 ah = __float2bfloat16(a), bh = __float2bfloat16(b);
    float ar = a - __bfloat162float(ah);
    float br = b - __bfloat162float(bh);
    __nv_bfloat16 al = __float2bfloat16(ar), bl = __float2bfloat16(br);
    hi = ((uint32_t)__bfloat16_as_ushort(bh) << 16) | (uint32_t)__bfloat16_as_ushort(ah);
    lo = ((uint32_t)__bfloat16_as_ushort(bl) << 16) | (uint32_t)__bfloat16_as_ushort(al);
}
__device__ __forceinline__ void mma16816(float* c, const uint32_t* a, const uint32_t* b) {
    asm volatile("mma.sync.aligned.m16n8k16.row.col.f32.bf16.bf16.f32 "
                 "{%0,%1,%2,%3}, {%4,%5,%6,%7}, {%8,%9}, {%0,%1,%2,%3};"
                 : "+f"(c[0]), "+f"(c[1]), "+f"(c[2]), "+f"(c[3])
                 : "r"(a[0]), "r"(a[1]), "r"(a[2]), "r"(a[3]), "r"(b[0]), "r"(b[1]));
}
__device__ __forceinline__ void ldsm_x4(uint32_t* r, uint32_t addr) {
    asm volatile("ldmatrix.sync.aligned.m8n8.x4.shared.b16 {%0,%1,%2,%3}, [%4];"
                 : "=r"(r[0]), "=r"(r[1]), "=r"(r[2]), "=r"(r[3]) : "r"(addr));
}

#define FMA8(av, b0, b1, ar) do {                                     \
    ar[0] = fmaf(av, b0.x, ar[0]); ar[1] = fmaf(av, b0.y, ar[1]);     \
    ar[2] = fmaf(av, b0.z, ar[2]); ar[3] = fmaf(av, b0.w, ar[3]);     \
    ar[4] = fmaf(av, b1.x, ar[4]); ar[5] = fmaf(av, b1.y, ar[5]);     \
    ar[6] = fmaf(av, b1.z, ar[6]); ar[7] = fmaf(av, b1.w, ar[7]); } while (0)

template<int KDIM, int LDA>
__device__ __forceinline__ void gemm_tile(const float* sA, const float* sB,
                                          int rl, int n0, float acc[8][8]) {
#pragma unroll 1
    for (int k4 = 0; k4 < KDIM; k4 += 4) {
        float4 a[8];
#pragma unroll
        for (int i = 0; i < 8; i++)
            a[i] = *(const float4*)(sA + (rl + i) * LDA + k4);
        float4 b00 = *(const float4*)(sB + (k4 + 0) * F + n0);
        float4 b01 = *(const float4*)(sB + (k4 + 0) * F + n0 + 4);
        float4 b10 = *(const float4*)(sB + (k4 + 1) * F + n0);
        float4 b11 = *(const float4*)(sB + (k4 + 1) * F + n0 + 4);
        float4 b20 = *(const float4*)(sB + (k4 + 2) * F + n0);
        float4 b21 = *(const float4*)(sB + (k4 + 2) * F + n0 + 4);
        float4 b30 = *(const float4*)(sB + (k4 + 3) * F + n0);
        float4 b31 = *(const float4*)(sB + (k4 + 3) * F + n0 + 4);
#pragma unroll
        for (int i = 0; i < 8; i++) {
            FMA8(a[i].x, b00, b01, acc[i]);
            FMA8(a[i].y, b10, b11, acc[i]);
            FMA8(a[i].z, b20, b21, acc[i]);
            FMA8(a[i].w, b30, b31, acc[i]);
        }
    }
}

// ---------------------------------------------------------------- prep weight images
__global__ void k_prep(const float* __restrict__ Wf1, const float* __restrict__ Wf2) {
    int idx = blockIdx.x * blockDim.x + threadIdx.x;
    if (idx < 16384) {                 // Wf2 [k=128][n=128] -> [n][k], swizzled 256B rows
        int k = idx >> 7, n = idx & 127;
        float w = Wf2[idx];
        __nv_bfloat16 h = __float2bfloat16(w);
        float r = w - __bfloat162float(h);
        uint32_t off = (uint32_t)n * 256u + ((uint32_t)((k >> 3) ^ (n & 7)) << 4) + (uint32_t)(k & 7) * 2u;
        *(__nv_bfloat16*)(g_W2T[0] + off) = h;
        *(__nv_bfloat16*)(g_W2T[1] + off) = __float2bfloat16(r);
    }
    if (idx < 4096) {                  // Wf1 [k=32][n=128] -> [n][k], 80B rows
        int k = idx >> 7, n = idx & 127;
        float w = Wf1[idx];
        __nv_bfloat16 h = __float2bfloat16(w);
        float r = w - __bfloat162float(h);
        uint32_t off = (uint32_t)n * 80u + (uint32_t)k * 2u;
        *(__nv_bfloat16*)(g_W1T[0] + off) = h;
        *(__nv_bfloat16*)(g_W1T[1] + off) = __float2bfloat16(r);
    }
}

// ---------------------------------------------------------------- zero acc
__global__ void k_zero(int n4) {
    int i = blockIdx.x * blockDim.x + threadIdx.x;
    if (i < n4) reinterpret_cast<float4*>(g_acc)[i] = make_float4(0.f, 0.f, 0.f, 0.f);
}

// ---------------------------------------------------------------- h = x @ W_in (SIMT fp32)
__global__ __launch_bounds__(NT, 1)
void k_input_proj(const float* __restrict__ x, const float* __restrict__ Win, int N) {
    extern __shared__ float sm[];
    float* sA = sm;
    float* sB = sm + F * F;
    const int tid = threadIdx.x;
    const int r0 = blockIdx.x * F;
    for (int t = tid; t < F * F / 4; t += NT) {
        int row = t >> 5, c4 = (t & 31) << 2;
        float4 v = make_float4(0.f, 0.f, 0.f, 0.f);
        if (r0 + row < N) v = *(const float4*)(x + (size_t)(r0 + row) * F + c4);
        *(float4*)(sA + row * F + c4) = v;
        *(float4*)(sB + row * F + c4) = *(const float4*)(Win + row * F + c4);
    }
    __syncthreads();
    const int tn = tid & 15, tp = tid >> 4;
    const int n0 = tn * 8, rl = tp * 8;
    float acc[8][8];
#pragma unroll
    for (int i = 0; i < 8; i++)
#pragma unroll
        for (int j = 0; j < 8; j++) acc[i][j] = 0.f;
    gemm_tile<F, F>(sA, sB, rl, n0, acc);
#pragma unroll
    for (int i = 0; i < 8; i++) {
        int r = r0 + rl + i;
        if (r < N) {
            *(float4*)(g_h + (size_t)r * F + n0)     = make_float4(acc[i][0], acc[i][1], acc[i][2], acc[i][3]);
            *(float4*)(g_h + (size_t)r * F + n0 + 4) = make_float4(acc[i][4], acc[i][5], acc[i][6], acc[i][7]);
        }
    }
}

// ---------------------------------------------------------------- pair kernel (barrier-free tiles)
// SMEM: W2hi 32K | W2lo 32K | W1hi 10240 | W1lo 10240 | bf1 512 | bf2 512
#define SM_W2HI 0
#define SM_W2LO 32768
#define SM_W1HI 65536
#define SM_W1LO 75776
#define SM_BF1  86016
#define SM_BF2  86528
#define SM_PAIR_TOTAL 87040

__global__ __launch_bounds__(256)
void k_pairs_mma(const float* __restrict__ f_ij, const float* __restrict__ fcut,
                 const int* __restrict__ pairlist, int P, int ntiles,
                 const float* __restrict__ bf1, const float* __restrict__ bf2) {
    extern __shared__ char smc[];
    const uint32_t sb = smem_u32(smc);
    const int tid  = threadIdx.x;
    const int wid  = tid >> 5;          // warp 0..7 -> rows 16*wid
    const int lane = tid & 31;
    const int l4 = lane >> 2;           // 0..7
    const int t2 = (lane & 3) * 2;      // 0,2,4,6
    const int mi = lane >> 3;           // 0..3 (ldmatrix matrix id)
    const int l8 = lane & 7;

    // ---- stage weights + biases into SMEM (once) ----
    {
        const uint4* s0 = (const uint4*)g_W2T[0]; uint4* d0 = (uint4*)(smc + SM_W2HI);
        for (int t = tid; t < 2048; t += 256) d0[t] = s0[t];
        const uint4* s1 = (const uint4*)g_W2T[1]; uint4* d1 = (uint4*)(smc + SM_W2LO);
        for (int t = tid; t < 2048; t += 256) d1[t] = s1[t];
        const uint4* s2 = (const uint4*)g_W1T[0]; uint4* d2 = (uint4*)(smc + SM_W1HI);
        for (int t = tid; t < 640; t += 256) d2[t] = s2[t];
        const uint4* s3 = (const uint4*)g_W1T[1]; uint4* d3 = (uint4*)(smc + SM_W1LO);
        for (int t = tid; t < 640; t += 256) d3[t] = s3[t];
        if (tid < 128) {
            ((float*)(smc + SM_BF1))[tid] = bf1[tid];
            ((float*)(smc + SM_BF2))[tid] = bf2[tid];
        }
    }
    const float* b1s = (const float*)(smc + SM_BF1);
    const float* b2s = (const float*)(smc + SM_BF2);
    __syncthreads();   // the ONLY block-wide barrier

    // W1 ldsm matrix base addresses (per-lane, tile-invariant):
    // for (ks, ng): addr = base + n*80 + kb*2, n = 16ng + (mi>>1)*8 + l8, kb = 16ks + (mi&1)*8
    const uint32_t w1n = (uint32_t)((mi >> 1) * 8 + l8) * 80u + (uint32_t)((mi & 1) * 8) * 2u;

    for (int tile = blockIdx.x; tile < ntiles; tile += gridDim.x) {
        const int p0 = tile * TP;
        const int rA = p0 + 16 * wid + l4;    // fragment rows: rA, rA+8
        const bool v0 = rA < P, v1 = rA + 8 < P;

        // prefetch epilogue metadata (overlaps stage-1)
        float cut0 = 0.f, cut1 = 0.f;
        int ai0 = 0, aj0 = 0, ai1 = 0, aj1 = 0;
        if (v0) { cut0 = __ldg(fcut + rA);     ai0 = __ldg(pairlist + rA);     aj0 = __ldg(pairlist + (size_t)P + rA); }
        if (v1) { cut1 = __ldg(fcut + rA + 8); ai1 = __ldg(pairlist + rA + 8); aj1 = __ldg(pairlist + (size_t)P + rA + 8); }

        float acc[16][4];
#pragma unroll
        for (int b = 0; b < 16; b++)
#pragma unroll
            for (int c = 0; c < 4; c++) acc[b][c] = 0.f;

        // ---- stage 1: S[16 x 128] = f_ij @ W1 (K=32), A from gmem ----
        const float* f0 = f_ij + (size_t)rA * R;
        const float* f1 = f0 + (size_t)8 * R;
#pragma unroll
        for (int ks = 0; ks < 2; ks++) {
            float2 q0 = make_float2(0.f, 0.f), q1 = q0, q2 = q0, q3 = q0;
            if (v0) { q0 = *(const float2*)(f0 + 16 * ks + t2); q2 = *(const float2*)(f0 + 16 * ks + t2 + 8); }
            if (v1) { q1 = *(const float2*)(f1 + 16 * ks + t2); q3 = *(const float2*)(f1 + 16 * ks + t2 + 8); }
            uint32_t ah[4], al[4];
            split_pack(q0.x, q0.y, ah[0], al[0]);
            split_pack(q1.x, q1.y, ah[1], al[1]);
            split_pack(q2.x, q2.y, ah[2], al[2]);
            split_pack(q3.x, q3.y, ah[3], al[3]);
            const uint32_t kofs = (uint32_t)(16 * ks) * 2u;
#pragma unroll
            for (int ng = 0; ng < 8; ng++) {
                uint32_t off = (uint32_t)(16 * ng) * 80u + w1n + kofs;
                uint32_t bh[4], bl[4];
                ldsm_x4(bh, sb + SM_W1HI + off);
                ldsm_x4(bl, sb + SM_W1LO + off);
                mma16816(acc[2 * ng],     ah, bh);
                mma16816(acc[2 * ng],     al, bh);
                mma16816(acc[2 * ng],     ah, bl);
                mma16816(acc[2 * ng + 1], ah, bh + 2);
                mma16816(acc[2 * ng + 1], al, bh + 2);
                mma16816(acc[2 * ng + 1], ah, bl + 2);
            }
        }

        // ---- ssp(S + bf1) -> bf16 hi/lo A-fragments (in registers; C->A layout identity) ----
        uint32_t a2hi[32], a2lo[32];
#pragma unroll
        for (int b = 0; b < 16; b++) {
            int c = 8 * b + t2;
            float e0 = sspf(acc[b][0] + b1s[c]);
            float e1 = sspf(acc[b][1] + b1s[c + 1]);
            float e2 = sspf(acc[b][2] + b1s[c]);
            float e3 = sspf(acc[b][3] + b1s[c + 1]);
            split_pack(e0, e1, a2hi[2 * b],     a2lo[2 * b]);
            split_pack(e2, e3, a2hi[2 * b + 1], a2lo[2 * b + 1]);
#pragma unroll
            for (int q = 0; q < 4; q++) acc[b][q] = 0.f;
        }

        // ---- stage 2: W_ij[16 x 128] = S @ W2 (K=128) ----
        const uint32_t w2n = ((uint32_t)((mi >> 1) * 8 + l8)) * 256u;
        const uint32_t n7  = (uint32_t)(((mi >> 1) * 8 + l8) & 7);
#pragma unroll
        for (int j = 0; j < 8; j++) {
            const uint32_t* ahf = a2hi + 4 * j;
            const uint32_t* alf = a2lo + 4 * j;
            const uint32_t kb = (uint32_t)(16 * j + (mi & 1) * 8);
#pragma unroll
            for (int ng = 0; ng < 8; ng++) {
                uint32_t off = (uint32_t)(16 * ng) * 256u + w2n + ((((kb >> 3)) ^ (((16 * ng) + ((mi >> 1) * 8 + l8)) & 7)) << 4);
                uint32_t bh[4], bl[4];
                ldsm_x4(bh, sb + SM_W2HI + off);
                ldsm_x4(bl, sb + SM_W2LO + off);
                mma16816(acc[2 * ng],     ahf, bh);
                mma16816(acc[2 * ng],     alf, bh);
                mma16816(acc[2 * ng],     ahf, bl);
                mma16816(acc[2 * ng + 1], ahf, bh + 2);
                mma16816(acc[2 * ng + 1], alf, bh + 2);
                mma16816(acc[2 * ng + 1], ahf, bl + 2);
            }
        }

        // ---- epilogue: (W_ij + bf2) * cut * h[idx_j] -> red_add g_acc[idx_i] ----
        if (v0) {
            const float* hrow = g_h + (size_t)aj0 * F;
            float* arow = g_acc + (size_t)ai0 * F;
#pragma unroll
            for (int b = 0; b < 16; b++) {
                int c = 8 * b + t2;
                float2 hv = *(const float2*)(hrow + c);
                float vx = (acc[b][0] + b2s[c])     * cut0 * hv.x;
                float vy = (acc[b][1] + b2s[c + 1]) * cut0 * hv.y;
                red_add_v2(arow + c, vx, vy);
            }
        }
        if (v1) {
            const float* hrow = g_h + (size_t)aj1 * F;
            float* arow = g_acc + (size_t)ai1 * F;
#pragma unroll
            for (int b = 0; b < 16; b++) {
                int c = 8 * b + t2;
                float2 hv = *(const float2*)(hrow + c);
                float vx = (acc[b][2] + b2s[c])     * cut1 * hv.x;
                float vy = (acc[b][3] + b2s[c + 1]) * cut1 * hv.y;
                red_add_v2(arow + c, vx, vy);
            }
        }
    }
}

// ---------------------------------------------------------------- out = ssp(acc@Wo1+bo1)@Wo2 + bo2 (SIMT fp32)
__global__ __launch_bounds__(NT, 1)
void k_output(const float* __restrict__ Wo1, const float* __restrict__ bo1,
              const float* __restrict__ Wo2, const float* __restrict__ bo2,
              float* __restrict__ out, int N) {
    extern __shared__ float sm[];
    float* sA = sm;
    float* sW = sA + F * F;
    float* sT = sW + F * F;
    float* sb = sT + F * F;
    const int tid = threadIdx.x;
    const int r0 = blockIdx.x * F;
    for (int t = tid; t < F * F / 4; t += NT) {
        int row = t >> 5, c4 = (t & 31) << 2;
        float4 v = make_float4(0.f, 0.f, 0.f, 0.f);
        if (r0 + row < N) v = *(const float4*)(g_acc + (size_t)(r0 + row) * F + c4);
        *(float4*)(sA + row * F + c4) = v;
        *(float4*)(sW + row * F + c4) = *(const float4*)(Wo1 + row * F + c4);
    }
    if (tid < F) { sb[tid] = bo1[tid]; sb[F + tid] = bo2[tid]; }
    __syncthreads();
    const int tn = tid & 15, tp = tid >> 4;
    const int n0 = tn * 8, rl = tp * 8;
    float acc[8][8];
#pragma unroll
    for (int i = 0; i < 8; i++)
#pragma unroll
        for (int j = 0; j < 8; j++) acc[i][j] = 0.f;
    gemm_tile<F, F>(sA, sW, rl, n0, acc);
    float4 bb0 = *(const float4*)(sb + n0);
    float4 bb1 = *(const float4*)(sb + n0 + 4);
#pragma unroll
    for (int i = 0; i < 8; i++) {
        float4 v0, v1;
        v0.x = sspf(acc[i][0] + bb0.x); v0.y = sspf(acc[i][1] + bb0.y);
        v0.z = sspf(acc[i][2] + bb0.z); v0.w = sspf(acc[i][3] + bb0.w);
        v1.x = sspf(acc[i][4] + bb1.x); v1.y = sspf(acc[i][5] + bb1.y);
        v1.z = sspf(acc[i][6] + bb1.z); v1.w = sspf(acc[i][7] + bb1.w);
        *(float4*)(sT + (rl + i) * F + n0)     = v0;
        *(float4*)(sT + (rl + i) * F + n0 + 4) = v1;
#pragma unroll
        for (int j = 0; j < 8; j++) acc[i][j] = 0.f;
    }
    __syncthreads();
    for (int t = tid; t < F * F / 4; t += NT) {
        int row = t >> 5, c4 = (t & 31) << 2;
        *(float4*)(sW + row * F + c4) = *(const float4*)(Wo2 + row * F + c4);
    }
    __syncthreads();
    gemm_tile<F, F>(sT, sW, rl, n0, acc);
    float4 d0 = *(const float4*)(sb + F + n0);
    float4 d1 = *(const float4*)(sb + F + n0 + 4);
#pragma unroll
    for (int i = 0; i < 8; i++) {
        int r = r0 + rl + i;
        if (r < N) {
            *(float4*)(out + (size_t)r * F + n0) =
                make_float4(acc[i][0] + d0.x, acc[i][1] + d0.y, acc[i][2] + d0.z, acc[i][3] + d0.w);
            *(float4*)(out + (size_t)r * F + n0 + 4) =
                make_float4(acc[i][4] + d1.x, acc[i][5] + d1.y, acc[i][6] + d1.z, acc[i][7] + d1.w);
        }
    }
}

// ----------------------------------------------------------------- launcher
extern "C" void kernel_launch(void* const* d_in, const int* in_sizes, int n_in,
                              void* d_out, int out_size) {
    const float* x    = (const float*)d_in[0];
    const int*   pl   = (const int*)  d_in[1];
    const float* f_ij = (const float*)d_in[2];
    const float* fcut = (const float*)d_in[3];
    const float* Win  = (const float*)d_in[4];
    const float* Wf1  = (const float*)d_in[5];
    const float* bf1  = (const float*)d_in[6];
    const float* Wf2  = (const float*)d_in[7];
    const float* bf2  = (const float*)d_in[8];
    const float* Wo1  = (const float*)d_in[9];
    const float* bo1  = (const float*)d_in[10];
    const float* Wo2  = (const float*)d_in[11];
    const float* bo2  = (const float*)d_in[12];
    float* out = (float*)d_out;

    const int N = in_sizes[0] / F;
    const int P = in_sizes[1] / 2;
    const int ntiles = (P + TP - 1) / TP;

    const int smem_proj = 2 * F * F * 4;
    const int smem_out  = 3 * F * F * 4 + 2 * F * 4;

    cudaFuncSetAttribute(k_input_proj, cudaFuncAttributeMaxDynamicSharedMemorySize, smem_proj);
    cudaFuncSetAttribute(k_pairs_mma,  cudaFuncAttributeMaxDynamicSharedMemorySize, SM_PAIR_TOTAL);
    cudaFuncSetAttribute(k_output,     cudaFuncAttributeMaxDynamicSharedMemorySize, smem_out);

    const int n4 = N * F / 4;
    k_prep<<<64, 256>>>(Wf1, Wf2);
    k_zero<<<(n4 + 255) / 256, 256>>>(n4);
    k_input_proj<<<(N + F - 1) / F, NT, smem_proj>>>(x, Win, N);
    int grid = ntiles < 296 ? ntiles : 296;
    k_pairs_mma<<<grid, 256, SM_PAIR_TOTAL>>>(f_ij, fcut, pl, P, ntiles, bf1, bf2);
    k_output<<<(N + F - 1) / F, NT, smem_out>>>(Wo1, bo1, Wo2, bo2, out, N);
}

// round 8
// speedup vs baseline: 1.4888x; 1.4888x over previous
#include <cuda_runtime.h>
#include <cuda_bf16.h>
#include <cstdint>
#include <math.h>

#define F   128
#define R   32
#define TP  64       // pairs per tile in k_pairs
#define NT  256

// ---------------------------------------------------------------- scratch
__device__ float g_h  [100000 * 128];
__device__ float g_acc[100000 * 128];
__device__ unsigned char g_W2T [2][32768];  // Wf2^T  [n][k] bf16 hi/lo, 256B rows, XOR-swizzled
__device__ unsigned char g_WinT[2][32768];  // W_in^T
__device__ unsigned char g_Wo1T[2][32768];  // Wo1^T
__device__ unsigned char g_Wo2T[2][32768];  // Wo2^T

// ---------------------------------------------------------------- helpers
__device__ __forceinline__ uint32_t smem_u32(const void* p) {
    uint32_t a;
    asm("{ .reg .u64 t; cvta.to.shared.u64 t, %1; cvt.u32.u64 %0, t; }" : "=r"(a) : "l"(p));
    return a;
}
__device__ __forceinline__ void barn(int id) {          // named barrier, 128 threads
    asm volatile("bar.sync %0, %1;" :: "r"(id), "r"(128) : "memory");
}
__device__ __forceinline__ float sspf(float x) {
    float e = __expf(-fabsf(x));
    return fmaxf(x, 0.0f) + __logf(1.0f + e) - 0.6931471805599453f;
}
__device__ __forceinline__ void red_add_v2(float* p, float a, float b) {
    asm volatile("red.global.add.v2.f32 [%0], {%1,%2};"
                 :: "l"(p), "f"(a), "f"(b) : "memory");
}
__device__ __forceinline__ void split_pack(float a, float b, uint32_t& hi, uint32_t& lo) {
    __nv_bfloat16 ah = __float2bfloat16(a), bh = __float2bfloat16(b);
    float ar = a - __bfloat162float(ah);
    float br = b - __bfloat162float(bh);
    __nv_bfloat16 al = __float2bfloat16(ar), bl = __float2bfloat16(br);
    hi = ((uint32_t)__bfloat16_as_ushort(bh) << 16) | (uint32_t)__bfloat16_as_ushort(ah);
    lo = ((uint32_t)__bfloat16_as_ushort(bl) << 16) | (uint32_t)__bfloat16_as_ushort(al);
}
__device__ __forceinline__ void mma16816(float* c, const uint32_t* a, const uint32_t* b) {
    asm volatile("mma.sync.aligned.m16n8k16.row.col.f32.bf16.bf16.f32 "
                 "{%0,%1,%2,%3}, {%4,%5,%6,%7}, {%8,%9}, {%0,%1,%2,%3};"
                 : "+f"(c[0]), "+f"(c[1]), "+f"(c[2]), "+f"(c[3])
                 : "r"(a[0]), "r"(a[1]), "r"(a[2]), "r"(a[3]), "r"(b[0]), "r"(b[1]));
}
__device__ __forceinline__ void ldsm_x4(uint32_t* r, uint32_t addr) {
    asm volatile("ldmatrix.sync.aligned.m8n8.x4.shared.b16 {%0,%1,%2,%3}, [%4];"
                 : "=r"(r[0]), "=r"(r[1]), "=r"(r[2]), "=r"(r[3]) : "r"(addr));
}
// interleaved 3-term split MMA: chains c0/c1 alternate (dep distance 2)
#define MMA6(c0, c1, ah, al, bh, bl) do {          \
    mma16816(c0, ah, bh);                          \
    mma16816(c1, ah, (bh) + 2);                    \
    mma16816(c0, al, bh);                          \
    mma16816(c1, al, (bh) + 2);                    \
    mma16816(c0, ah, bl);                          \
    mma16816(c1, ah, (bl) + 2); } while (0)

// ---------------------------------------------------------------- prep: 4 swizzled weight images
__global__ void k_prep(const float* __restrict__ Wf2, const float* __restrict__ Win,
                       const float* __restrict__ Wo1, const float* __restrict__ Wo2) {
    int idx = blockIdx.x * blockDim.x + threadIdx.x;
    if (idx >= 16384) return;
    int k = idx >> 7, n = idx & 127;
    uint32_t off = (uint32_t)n * 256u + ((uint32_t)((k >> 3) ^ (n & 7)) << 4) + (uint32_t)(k & 7) * 2u;
    {
        float w = Wf2[idx];
        __nv_bfloat16 h = __float2bfloat16(w);
        *(__nv_bfloat16*)(g_W2T[0] + off) = h;
        *(__nv_bfloat16*)(g_W2T[1] + off) = __float2bfloat16(w - __bfloat162float(h));
    }
    {
        float w = Win[idx];
        __nv_bfloat16 h = __float2bfloat16(w);
        *(__nv_bfloat16*)(g_WinT[0] + off) = h;
        *(__nv_bfloat16*)(g_WinT[1] + off) = __float2bfloat16(w - __bfloat162float(h));
    }
    {
        float w = Wo1[idx];
        __nv_bfloat16 h = __float2bfloat16(w);
        *(__nv_bfloat16*)(g_Wo1T[0] + off) = h;
        *(__nv_bfloat16*)(g_Wo1T[1] + off) = __float2bfloat16(w - __bfloat162float(h));
    }
    {
        float w = Wo2[idx];
        __nv_bfloat16 h = __float2bfloat16(w);
        *(__nv_bfloat16*)(g_Wo2T[0] + off) = h;
        *(__nv_bfloat16*)(g_Wo2T[1] + off) = __float2bfloat16(w - __bfloat162float(h));
    }
}

// ---------------------------------------------------------------- zero acc
__global__ void k_zero(int n4) {
    int i = blockIdx.x * blockDim.x + threadIdx.x;
    if (i < n4) reinterpret_cast<float4*>(g_acc)[i] = make_float4(0.f, 0.f, 0.f, 0.f);
}

// ---------------------------------------------------------------- h = x @ W_in (mma bf16-split)
#define SMI_HI 0
#define SMI_LO 32768
#define SMI_TOTAL 65536
__global__ __launch_bounds__(256, 2)
void k_input_mma(const float* __restrict__ x, int N) {
    extern __shared__ char smc[];
    const uint32_t sb = smem_u32(smc);
    const int tid = threadIdx.x, wid = tid >> 5, lane = tid & 31;
    const int l4 = lane >> 2, t2 = (lane & 3) * 2, mi = lane >> 3, l8 = lane & 7;
    {
        const uint4* s0 = (const uint4*)g_WinT[0]; uint4* d0 = (uint4*)(smc + SMI_HI);
        for (int t = tid; t < 2048; t += 256) d0[t] = s0[t];
        const uint4* s1 = (const uint4*)g_WinT[1]; uint4* d1 = (uint4*)(smc + SMI_LO);
        for (int t = tid; t < 2048; t += 256) d1[t] = s1[t];
    }
    __syncthreads();

    const int rA = blockIdx.x * 128 + 16 * wid + l4;
    const bool v0 = rA < N, v1 = rA + 8 < N;
    const uint32_t w2n = (uint32_t)((mi >> 1) * 8 + l8) * 256u;

    float acc[16][4];
#pragma unroll
    for (int b = 0; b < 16; b++)
#pragma unroll
        for (int c = 0; c < 4; c++) acc[b][c] = 0.f;

    const float* x0 = x + (size_t)rA * F;
    const float* x1 = x0 + (size_t)8 * F;
#pragma unroll
    for (int j = 0; j < 8; j++) {
        float2 q0 = make_float2(0.f, 0.f), q1 = q0, q2 = q0, q3 = q0;
        if (v0) { q0 = *(const float2*)(x0 + 16 * j + t2); q2 = *(const float2*)(x0 + 16 * j + t2 + 8); }
        if (v1) { q1 = *(const float2*)(x1 + 16 * j + t2); q3 = *(const float2*)(x1 + 16 * j + t2 + 8); }
        uint32_t ah[4], al[4];
        split_pack(q0.x, q0.y, ah[0], al[0]);
        split_pack(q1.x, q1.y, ah[1], al[1]);
        split_pack(q2.x, q2.y, ah[2], al[2]);
        split_pack(q3.x, q3.y, ah[3], al[3]);
        const uint32_t kb = (uint32_t)(16 * j + (mi & 1) * 8);
        const uint32_t sw = (uint32_t)(((kb >> 3) ^ (uint32_t)l8) << 4);
#pragma unroll
        for (int ng = 0; ng < 8; ng++) {
            uint32_t off = (uint32_t)(16 * ng) * 256u + w2n + sw;
            uint32_t bh[4], bl[4];
            ldsm_x4(bh, sb + SMI_HI + off);
            ldsm_x4(bl, sb + SMI_LO + off);
            MMA6(acc[2 * ng], acc[2 * ng + 1], ah, al, bh, bl);
        }
    }
#pragma unroll
    for (int b = 0; b < 16; b++) {
        int c = 8 * b + t2;
        if (v0) *(float2*)(g_h + (size_t)rA * F + c)       = make_float2(acc[b][0], acc[b][1]);
        if (v1) *(float2*)(g_h + (size_t)(rA + 8) * F + c) = make_float2(acc[b][2], acc[b][3]);
    }
}

// ---------------------------------------------------------------- pair kernel (R4 + named barriers + reorder)
#define SM_W2HI 0
#define SM_W2LO 32768
#define SM_A2HI 65536
#define SM_A2LO 81920
#define SM_BF1  98304
#define SM_BF2  98816
#define SM_PAIR_TOTAL 99328

__global__ __launch_bounds__(256, 2)
void k_pairs_mma(const float* __restrict__ f_ij, const float* __restrict__ fcut,
                 const int* __restrict__ pairlist, int P, int ntiles,
                 const float* __restrict__ Wf1,
                 const float* __restrict__ bf1, const float* __restrict__ bf2) {
    extern __shared__ char smc[];
    const uint32_t sb = smem_u32(smc);
    const int tid  = threadIdx.x;
    const int wid  = tid >> 5;
    const int lane = tid & 31;
    const int wm   = wid >> 2;          // 0..1  rows 32*wm (exchange group)
    const int wn   = wid & 3;           // 0..3  cols 32*wn
    const int rbase = 32 * wm;
    const int cbase = 32 * wn;
    const int g  = lane >> 2;
    const int t2 = (lane & 3) * 2;
    const int mi = lane >> 3;
    const int l8 = lane & 7;
    const int barid = 1 + wm;

    {
        const uint4* s0 = (const uint4*)g_W2T[0]; uint4* d0 = (uint4*)(smc + SM_W2HI);
        for (int t = tid; t < 2048; t += 256) d0[t] = s0[t];
        const uint4* s1 = (const uint4*)g_W2T[1]; uint4* d1 = (uint4*)(smc + SM_W2LO);
        for (int t = tid; t < 2048; t += 256) d1[t] = s1[t];
        if (tid < 128) {
            ((float*)(smc + SM_BF1))[tid] = bf1[tid];
            ((float*)(smc + SM_BF2))[tid] = bf2[tid];
        }
    }

    // W1 B-fragments in registers (once)
    uint32_t w1hi[2][2][4], w1lo[2][2][4];
#pragma unroll
    for (int ks = 0; ks < 2; ks++)
#pragma unroll
        for (int ng = 0; ng < 2; ng++)
#pragma unroll
            for (int h = 0; h < 2; h++) {
                int n = cbase + 16 * ng + 8 * h + g;
                int k = 16 * ks + t2;
                float b00 = __ldg(Wf1 + (size_t)k * F + n);
                float b01 = __ldg(Wf1 + (size_t)(k + 1) * F + n);
                float b10 = __ldg(Wf1 + (size_t)(k + 8) * F + n);
                float b11 = __ldg(Wf1 + (size_t)(k + 9) * F + n);
                split_pack(b00, b01, w1hi[ks][ng][2 * h],     w1lo[ks][ng][2 * h]);
                split_pack(b10, b11, w1hi[ks][ng][2 * h + 1], w1lo[ks][ng][2 * h + 1]);
            }

    const float* b1s = (const float*)(smc + SM_BF1);
    const float* b2s = (const float*)(smc + SM_BF2);
    __syncthreads();

    const int l4 = lane >> 2;
    const int l2 = (lane & 3) * 2;

    for (int tile = blockIdx.x; tile < ntiles; tile += gridDim.x) {
        const int p0 = tile * TP;

        float acc[2][4][4];
#pragma unroll
        for (int a = 0; a < 2; a++)
#pragma unroll
            for (int b = 0; b < 4; b++)
#pragma unroll
                for (int c = 0; c < 4; c++) acc[a][b][c] = 0.f;

        // ---- stage 1: S = f_ij @ W1 (K=32), A from gmem ----
#pragma unroll
        for (int ks = 0; ks < 2; ks++) {
            uint32_t ah[2][4], al[2][4];
#pragma unroll
            for (int mt = 0; mt < 2; mt++) {
                int r = p0 + rbase + 16 * mt + g;
                float2 v0 = make_float2(0.f, 0.f), v1 = v0, v2 = v0, v3 = v0;
                if (r < P) {
                    const float* fp = f_ij + (size_t)r * R + 16 * ks + t2;
                    v0 = *(const float2*)fp;
                    v2 = *(const float2*)(fp + 8);
                }
                if (r + 8 < P) {
                    const float* fp = f_ij + (size_t)(r + 8) * R + 16 * ks + t2;
                    v1 = *(const float2*)fp;
                    v3 = *(const float2*)(fp + 8);
                }
                split_pack(v0.x, v0.y, ah[mt][0], al[mt][0]);
                split_pack(v1.x, v1.y, ah[mt][1], al[mt][1]);
                split_pack(v2.x, v2.y, ah[mt][2], al[mt][2]);
                split_pack(v3.x, v3.y, ah[mt][3], al[mt][3]);
            }
#pragma unroll
            for (int ng = 0; ng < 2; ng++)
#pragma unroll
                for (int mt = 0; mt < 2; mt++)
                    MMA6(acc[mt][2 * ng], acc[mt][2 * ng + 1], ah[mt], al[mt],
                         w1hi[ks][ng], w1lo[ks][ng]);
        }

        barn(barid);   // group's previous-tile stage-2 reads of A2 done

        // ---- ssp(S + bf1) -> split -> A2 smem (swizzled), reset acc ----
#pragma unroll
        for (int mt = 0; mt < 2; mt++)
#pragma unroll
            for (int nt = 0; nt < 4; nt++) {
                int c = cbase + 8 * nt + l2;
#pragma unroll
                for (int half = 0; half < 2; half++) {
                    int r = rbase + 16 * mt + l4 + 8 * half;
                    float e0 = sspf(acc[mt][nt][2 * half]     + b1s[c]);
                    float e1 = sspf(acc[mt][nt][2 * half + 1] + b1s[c + 1]);
                    uint32_t hi, lo;
                    split_pack(e0, e1, hi, lo);
                    uint32_t off = (uint32_t)r * 256u + ((uint32_t)((c >> 3) ^ (r & 7)) << 4) + (uint32_t)(c & 7) * 2u;
                    *(uint32_t*)(smc + SM_A2HI + off) = hi;
                    *(uint32_t*)(smc + SM_A2LO + off) = lo;
                }
            }
#pragma unroll
        for (int a = 0; a < 2; a++)
#pragma unroll
            for (int b = 0; b < 4; b++)
#pragma unroll
                for (int c = 0; c < 4; c++) acc[a][b][c] = 0.f;

        barn(barid);   // A2 visible within group

        // ---- stage 2: W_ij = S @ W2 (K=128) ----
#pragma unroll 1
        for (int ks = 0; ks < 8; ks++) {
            const int k0 = ks * 16;
            uint32_t ah[2][4], al[2][4];
#pragma unroll
            for (int mt = 0; mt < 2; mt++) {
                int r  = rbase + 16 * mt + (mi & 1) * 8 + l8;
                int kb = k0 + (mi >> 1) * 8;
                uint32_t off = (uint32_t)r * 256u + ((uint32_t)((kb >> 3) ^ (r & 7)) << 4);
                ldsm_x4(ah[mt], sb + SM_A2HI + off);
                ldsm_x4(al[mt], sb + SM_A2LO + off);
            }
#pragma unroll
            for (int ng = 0; ng < 2; ng++) {
                int n  = cbase + 16 * ng + (mi >> 1) * 8 + l8;
                int kb = k0 + (mi & 1) * 8;
                uint32_t off = (uint32_t)n * 256u + ((uint32_t)((kb >> 3) ^ (n & 7)) << 4);
                uint32_t bh[4], bl[4];
                ldsm_x4(bh, sb + SM_W2HI + off);
                ldsm_x4(bl, sb + SM_W2LO + off);
#pragma unroll
                for (int mt = 0; mt < 2; mt++)
                    MMA6(acc[mt][2 * ng], acc[mt][2 * ng + 1], ah[mt], al[mt], bh, bl);
            }
        }

        // ---- epilogue ----
#pragma unroll
        for (int mt = 0; mt < 2; mt++)
#pragma unroll
            for (int half = 0; half < 2; half++) {
                int rl = rbase + 16 * mt + l4 + 8 * half;
                int p  = p0 + rl;
                if (p < P) {
                    float cu = __ldg(fcut + p);
                    int ai = __ldg(pairlist + p);
                    int aj = __ldg(pairlist + (size_t)P + p);
                    const float* hrow = g_h + (size_t)aj * F;
                    float* arow = g_acc + (size_t)ai * F;
#pragma unroll
                    for (int nt = 0; nt < 4; nt++) {
                        int c = cbase + 8 * nt + l2;
                        float2 hv = *(const float2*)(hrow + c);
                        float vx = (acc[mt][nt][2 * half]     + b2s[c])     * cu * hv.x;
                        float vy = (acc[mt][nt][2 * half + 1] + b2s[c + 1]) * cu * hv.y;
                        red_add_v2(arow + c, vx, vy);
                    }
                }
            }
    }
}

// ---------------------------------------------------------------- out = ssp(acc@Wo1+bo1)@Wo2 + bo2 (mma, register C->A identity)
#define SMO_1HI 0
#define SMO_1LO 32768
#define SMO_2HI 65536
#define SMO_2LO 98304
#define SMO_BO1 131072
#define SMO_BO2 131584
#define SMO_TOTAL 132096
__global__ __launch_bounds__(256, 1)
void k_output_mma(const float* __restrict__ bo1, const float* __restrict__ bo2,
                  float* __restrict__ out, int N) {
    extern __shared__ char smc[];
    const uint32_t sb = smem_u32(smc);
    const int tid = threadIdx.x, wid = tid >> 5, lane = tid & 31;
    const int l4 = lane >> 2, t2 = (lane & 3) * 2, mi = lane >> 3, l8 = lane & 7;
    {
        const uint4* s0 = (const uint4*)g_Wo1T[0]; uint4* d0 = (uint4*)(smc + SMO_1HI);
        for (int t = tid; t < 2048; t += 256) d0[t] = s0[t];
        const uint4* s1 = (const uint4*)g_Wo1T[1]; uint4* d1 = (uint4*)(smc + SMO_1LO);
        for (int t = tid; t < 2048; t += 256) d1[t] = s1[t];
        const uint4* s2 = (const uint4*)g_Wo2T[0]; uint4* d2 = (uint4*)(smc + SMO_2HI);
        for (int t = tid; t < 2048; t += 256) d2[t] = s2[t];
        const uint4* s3 = (const uint4*)g_Wo2T[1]; uint4* d3 = (uint4*)(smc + SMO_2LO);
        for (int t = tid; t < 2048; t += 256) d3[t] = s3[t];
        if (tid < 128) {
            ((float*)(smc + SMO_BO1))[tid] = bo1[tid];
            ((float*)(smc + SMO_BO2))[tid] = bo2[tid];
        }
    }
    __syncthreads();

    const int rA = blockIdx.x * 128 + 16 * wid + l4;
    const bool v0 = rA < N, v1 = rA + 8 < N;
    const uint32_t w2n = (uint32_t)((mi >> 1) * 8 + l8) * 256u;
    const float* b1s = (const float*)(smc + SMO_BO1);
    const float* b2s = (const float*)(smc + SMO_BO2);

    float acc[16][4];
#pragma unroll
    for (int b = 0; b < 16; b++)
#pragma unroll
        for (int c = 0; c < 4; c++) acc[b][c] = 0.f;

    // ---- stage 1: T = g_acc @ Wo1 (K=128), A from gmem ----
    const float* a0 = g_acc + (size_t)rA * F;
    const float* a1 = a0 + (size_t)8 * F;
#pragma unroll
    for (int j = 0; j < 8; j++) {
        float2 q0 = make_float2(0.f, 0.f), q1 = q0, q2 = q0, q3 = q0;
        if (v0) { q0 = *(const float2*)(a0 + 16 * j + t2); q2 = *(const float2*)(a0 + 16 * j + t2 + 8); }
        if (v1) { q1 = *(const float2*)(a1 + 16 * j + t2); q3 = *(const float2*)(a1 + 16 * j + t2 + 8); }
        uint32_t ah[4], al[4];
        split_pack(q0.x, q0.y, ah[0], al[0]);
        split_pack(q1.x, q1.y, ah[1], al[1]);
        split_pack(q2.x, q2.y, ah[2], al[2]);
        split_pack(q3.x, q3.y, ah[3], al[3]);
        const uint32_t kb = (uint32_t)(16 * j + (mi & 1) * 8);
        const uint32_t sw = (uint32_t)(((kb >> 3) ^ (uint32_t)l8) << 4);
#pragma unroll
        for (int ng = 0; ng < 8; ng++) {
            uint32_t off = (uint32_t)(16 * ng) * 256u + w2n + sw;
            uint32_t bh[4], bl[4];
            ldsm_x4(bh, sb + SMO_1HI + off);
            ldsm_x4(bl, sb + SMO_1LO + off);
            MMA6(acc[2 * ng], acc[2 * ng + 1], ah, al, bh, bl);
        }
    }

    // ---- ssp(T + bo1) -> A-fragments in registers (C->A identity) ----
    uint32_t a2hi[32], a2lo[32];
#pragma unroll
    for (int b = 0; b < 16; b++) {
        int c = 8 * b + t2;
        float e0 = sspf(acc[b][0] + b1s[c]);
        float e1 = sspf(acc[b][1] + b1s[c + 1]);
        float e2 = sspf(acc[b][2] + b1s[c]);
        float e3 = sspf(acc[b][3] + b1s[c + 1]);
        split_pack(e0, e1, a2hi[2 * b],     a2lo[2 * b]);
        split_pack(e2, e3, a2hi[2 * b + 1], a2lo[2 * b + 1]);
#pragma unroll
        for (int q = 0; q < 4; q++) acc[b][q] = 0.f;
    }

    // ---- stage 2: out = T @ Wo2 (K=128) ----
#pragma unroll
    for (int j = 0; j < 8; j++) {
        const uint32_t* ahf = a2hi + 4 * j;
        const uint32_t* alf = a2lo + 4 * j;
        const uint32_t kb = (uint32_t)(16 * j + (mi & 1) * 8);
        const uint32_t sw = (uint32_t)(((kb >> 3) ^ (uint32_t)l8) << 4);
#pragma unroll
        for (int ng = 0; ng < 8; ng++) {
            uint32_t off = (uint32_t)(16 * ng) * 256u + w2n + sw;
            uint32_t bh[4], bl[4];
            ldsm_x4(bh, sb + SMO_2HI + off);
            ldsm_x4(bl, sb + SMO_2LO + off);
            MMA6(acc[2 * ng], acc[2 * ng + 1], ahf, alf, bh, bl);
        }
    }

#pragma unroll
    for (int b = 0; b < 16; b++) {
        int c = 8 * b + t2;
        if (v0) *(float2*)(out + (size_t)rA * F + c) =
            make_float2(acc[b][0] + b2s[c], acc[b][1] + b2s[c + 1]);
        if (v1) *(float2*)(out + (size_t)(rA + 8) * F + c) =
            make_float2(acc[b][2] + b2s[c], acc[b][3] + b2s[c + 1]);
    }
}

// ----------------------------------------------------------------- launcher
extern "C" void kernel_launch(void* const* d_in, const int* in_sizes, int n_in,
                              void* d_out, int out_size) {
    const float* x    = (const float*)d_in[0];
    const int*   pl   = (const int*)  d_in[1];
    const float* f_ij = (const float*)d_in[2];
    const float* fcut = (const float*)d_in[3];
    const float* Win  = (const float*)d_in[4];
    const float* Wf1  = (const float*)d_in[5];
    const float* bf1  = (const float*)d_in[6];
    const float* Wf2  = (const float*)d_in[7];
    const float* bf2  = (const float*)d_in[8];
    const float* Wo1  = (const float*)d_in[9];
    const float* bo1  = (const float*)d_in[10];
    const float* Wo2  = (const float*)d_in[11];
    const float* bo2  = (const float*)d_in[12];
    float* out = (float*)d_out;

    const int N = in_sizes[0] / F;
    const int P = in_sizes[1] / 2;
    const int ntiles = (P + TP - 1) / TP;
    const int nrow_tiles = (N + 127) / 128;

    cudaFuncSetAttribute(k_input_mma,  cudaFuncAttributeMaxDynamicSharedMemorySize, SMI_TOTAL);
    cudaFuncSetAttribute(k_pairs_mma,  cudaFuncAttributeMaxDynamicSharedMemorySize, SM_PAIR_TOTAL);
    cudaFuncSetAttribute(k_output_mma, cudaFuncAttributeMaxDynamicSharedMemorySize, SMO_TOTAL);

    const int n4 = N * F / 4;
    k_prep<<<64, 256>>>(Wf2, Win, Wo1, Wo2);
    k_zero<<<(n4 + 255) / 256, 256>>>(n4);
    k_input_mma<<<nrow_tiles, 256, SMI_TOTAL>>>(x, N);
    int grid = ntiles < 296 ? ntiles : 296;
    k_pairs_mma<<<grid, 256, SM_PAIR_TOTAL>>>(f_ij, fcut, pl, P, ntiles, Wf1, bf1, bf2);
    k_output_mma<<<nrow_tiles, 256, SMO_TOTAL>>>(bo1, bo2, out, N);
}